// round 6
// baseline (speedup 1.0000x reference)
#include <cuda_runtime.h>
#include <cstdint>

#define NPROP 1024
#define NCLS  81
#define NC1   80
#define BIMG  2
#define DOUT  100
#define SCORE_TH 0.05f
#define NMS_TH   0.5f
#define IMG_MAX  1023.0f   // W - TO_REMOVE
#define NCAND (NC1 * NPROP)
#define TOPK_P 4096        // final-sort capacity (32KB smem)
#define NB 148             // grid size: <= SM count -> all CTAs resident (wave 1)
#define NT 256

typedef unsigned long long u64;

// ---------------- device scratch (no allocations allowed) ----------------
__device__ float2 g_rowstat[BIMG * NPROP];       // {rowmax, 1/sum(exp)}
__device__ int    g_cand_cnt[BIMG];
__device__ u64    g_cand_key[BIMG][NCAND];       // (score_bits<<32) | ~flat
__device__ unsigned g_bar1, g_bar2, g_bar3;      // zero-initialized at load

// ---------------- grid barrier (all 148 CTAs resident => no deadlock) -----
__device__ __forceinline__ void grid_barrier(unsigned* bar) {
    __syncthreads();
    if (threadIdx.x == 0) {
        __threadfence();                 // release my writes (gpu scope, flushes L1)
        atomicAdd(bar, 1u);
        volatile unsigned* vb = (volatile unsigned*)bar;
        while (*vb < NB) { }
        __threadfence();                 // acquire others' writes
    }
    __syncthreads();
}

// ---------------- exact maskrcnn-benchmark decode ----------------
__device__ __forceinline__ float4 decode_box(const float* __restrict__ reg,
                                             const float* __restrict__ props,
                                             int b, int n, int c0) {
    const float BBOX_CLIP = 4.135166556742356f;   // log(1000/16)
    const float* p4 = props + (size_t)(b * NPROP + n) * 4;
    float x1 = p4[0], y1 = p4[1], x2 = p4[2], y2 = p4[3];
    float w  = x2 - x1 + 1.f, h = y2 - y1 + 1.f;
    float cx = x1 + 0.5f * w,  cy = y1 + 0.5f * h;
    const float* r4 = reg + ((size_t)(b * NPROP + n) * NCLS + (c0 + 1)) * 4;
    float dx = r4[0] / 10.f, dy = r4[1] / 10.f;
    float dw = fminf(r4[2] / 5.f, BBOX_CLIP);
    float dh = fminf(r4[3] / 5.f, BBOX_CLIP);
    float pcx = dx * w + cx, pcy = dy * h + cy;
    float pw = expf(dw) * w, ph = expf(dh) * h;
    float nx1 = fminf(fmaxf(pcx - 0.5f * pw, 0.f), IMG_MAX);
    float ny1 = fminf(fmaxf(pcy - 0.5f * ph, 0.f), IMG_MAX);
    float nx2 = fminf(fmaxf(pcx + 0.5f * pw - 1.f, 0.f), IMG_MAX);
    float ny2 = fminf(fmaxf(pcy + 0.5f * ph - 1.f, 0.f), IMG_MAX);
    return make_float4(nx1, ny1, nx2, ny2);
}

// ---------------- fused kernel ----------------
__global__ void __launch_bounds__(NT, 1)
k_fused(const float* __restrict__ logits, const float* __restrict__ reg,
        const float* __restrict__ props, float* __restrict__ out) {
    // 32KB buffer: phase2 aliases {skey 8K | sbox 16K | skeep 1K}, phase3 aliases sk[4096]
    __shared__ __align__(16) char s_raw[TOPK_P * 8];
    __shared__ u64 rk[NT];
    __shared__ int ri[NT];
    __shared__ int scnt;
    u64*           skey  = (u64*)s_raw;
    float4*        sbox  = (float4*)(s_raw + 8192);
    unsigned char* skeep = (unsigned char*)(s_raw + 8192 + 16384);
    u64*           sk    = (u64*)s_raw;

    int tid = threadIdx.x;
    int bid = blockIdx.x;

    // ================= phase 1: per-row softmax stats =================
    if (bid == 0 && tid < BIMG) g_cand_cnt[tid] = 0;
    {
        int lane = tid & 31;
        for (int row = bid * (NT / 32) + (tid >> 5); row < BIMG * NPROP; row += NB * (NT / 32)) {
            const float* rp = logits + (size_t)row * NCLS;
            float v0 = rp[lane];
            float v1 = (lane + 32 < NCLS) ? rp[lane + 32] : -1e30f;
            float v2 = (lane + 64 < NCLS) ? rp[lane + 64] : -1e30f;
            float m = fmaxf(v0, fmaxf(v1, v2));
            #pragma unroll
            for (int o = 16; o; o >>= 1) m = fmaxf(m, __shfl_xor_sync(~0u, m, o));
            float e0 = expf(v0 - m);
            float e1 = (lane + 32 < NCLS) ? expf(v1 - m) : 0.f;
            float e2 = (lane + 64 < NCLS) ? expf(v2 - m) : 0.f;
            float s = e0 + e1 + e2;
            #pragma unroll
            for (int o = 16; o; o >>= 1) s += __shfl_xor_sync(~0u, s, o);
            if (lane == 0) g_rowstat[row] = make_float2(m, 1.f / s);
        }
    }
    grid_barrier(&g_bar1);

    // ================= phase 2: per-(image,class) compact+sort+decode+NMS =====
    for (int t = bid; t < BIMG * NC1; t += NB) {
        int b  = t / NC1;
        int c0 = t % NC1;                // class-1 index (skip background)
        if (tid == 0) scnt = 0;
        __syncthreads();

        // compact valid; key = (score_bits<<32) | (1023 - n)  (stable argsort match)
        const float*  lg = logits + (size_t)(b * NPROP) * NCLS + (c0 + 1);
        const float2* rs = g_rowstat + b * NPROP;
        for (int n = tid; n < NPROP; n += NT) {
            float2 st = rs[n];
            float s = expf(lg[(size_t)n * NCLS] - st.x) * st.y;
            if (s > SCORE_TH) {
                int p = atomicAdd(&scnt, 1);
                skey[p] = ((u64)__float_as_uint(s) << 32) | (unsigned)(NPROP - 1 - n);
            }
        }
        __syncthreads();
        int M = scnt;                    // uniform across block
        if (M > 0) {
            // bitonic sort, descending; pad with 0 sentinels
            int P = 1; while (P < M) P <<= 1;
            for (int i = M + tid; i < P; i += NT) skey[i] = 0ull;
            __syncthreads();
            for (int k = 2; k <= P; k <<= 1)
                for (int j = k >> 1; j > 0; j >>= 1) {
                    for (int i = tid; i < P; i += NT) {
                        int ixj = i ^ j;
                        if (ixj > i) {
                            bool up = ((i & k) != 0);
                            u64 a = skey[i], c = skey[ixj];
                            if ((a > c) == up) { skey[i] = c; skey[ixj] = a; }
                        }
                    }
                    __syncthreads();
                }

            // decode sorted candidates
            for (int i = tid; i < M; i += NT) {
                int n = NPROP - 1 - (int)(skey[i] & 0xFFFFFFFFu);
                sbox[i] = decode_box(reg, props, b, n, c0);
                skeep[i] = 1;
            }
            __syncthreads();

            // greedy NMS (score-descending); legacy +1 IoU
            for (int i = 0; i < M - 1; ++i) {
                if (skeep[i]) {
                    float4 bi = sbox[i];
                    float ai = (bi.z - bi.x + 1.f) * (bi.w - bi.y + 1.f);
                    for (int j = i + 1 + tid; j < M; j += NT) {
                        if (!skeep[j]) continue;
                        float4 bj = sbox[j];
                        float aj = (bj.z - bj.x + 1.f) * (bj.w - bj.y + 1.f);
                        float ix = fmaxf(fminf(bi.z, bj.z) - fmaxf(bi.x, bj.x) + 1.f, 0.f);
                        float iy = fmaxf(fminf(bi.w, bj.w) - fmaxf(bi.y, bj.y) + 1.f, 0.f);
                        float inter = ix * iy;
                        if (inter / (ai + aj - inter) > NMS_TH) skeep[j] = 0;
                    }
                }
                __syncthreads();
            }

            // append survivor keys
            for (int i = tid; i < M; i += NT) {
                if (!skeep[i]) continue;
                u64 key = skey[i];
                int n = NPROP - 1 - (int)(key & 0xFFFFFFFFu);
                unsigned flat = (unsigned)(c0 * NPROP + n);
                int pos = atomicAdd(&g_cand_cnt[b], 1);
                g_cand_key[b][pos] = (key & 0xFFFFFFFF00000000ull) | (unsigned)(~flat);
            }
        }
        __syncthreads();
    }
    grid_barrier(&g_bar2);

    // ================= phase 3: per-image top-100 (blocks 0..BIMG-1) =====
    if (bid < BIMG) {
        int b = bid;
        int K = g_cand_cnt[b];
        if (K <= TOPK_P) {
            for (int i = tid; i < TOPK_P; i += NT)
                sk[i] = (i < K) ? g_cand_key[b][i] : 0ull;
            __syncthreads();
            int P = 2; while (P < K) P <<= 1;
            for (int k = 2; k <= P; k <<= 1)
                for (int j = k >> 1; j > 0; j >>= 1) {
                    for (int i = tid; i < P; i += NT) {
                        int ixj = i ^ j;
                        if (ixj > i) {
                            bool up = ((i & k) != 0);
                            u64 a = sk[i], c = sk[ixj];
                            if ((a > c) == up) { sk[i] = c; sk[ixj] = a; }
                        }
                    }
                    __syncthreads();
                }
        } else {
            // fallback (never expected): iterative selection into sk[0..D)
            for (int d = 0; d < DOUT; ++d) {
                u64 best = 0; int bidx = -1;
                for (int i = tid; i < K; i += NT) {
                    u64 key = g_cand_key[b][i];
                    if (key > best) { best = key; bidx = i; }
                }
                rk[tid] = best; ri[tid] = bidx;
                __syncthreads();
                for (int o = NT / 2; o > 0; o >>= 1) {
                    if (tid < o && rk[tid + o] > rk[tid]) { rk[tid] = rk[tid + o]; ri[tid] = ri[tid + o]; }
                    __syncthreads();
                }
                if (tid == 0) {
                    sk[d] = rk[0];
                    if (ri[0] >= 0) g_cand_key[b][ri[0]] = 0ull;
                }
                __syncthreads();
            }
        }

        // emit: boxes [B,D,4] | scores [B,D] | labels [B,D]
        if (tid < DOUT) {
            u64 key = (tid < K || K > TOPK_P) ? sk[tid] : 0ull;
            float4 bx = make_float4(0.f, 0.f, 0.f, 0.f);
            float sc = 0.f, lb = -1.f;
            if (key != 0ull) {
                unsigned flat = ~(unsigned)(key & 0xFFFFFFFFu);
                int c0 = flat / NPROP, n = flat % NPROP;
                bx = decode_box(reg, props, b, n, c0);
                sc = __uint_as_float((unsigned)(key >> 32));
                lb = (float)(c0 + 1);
            }
            float* ob = out + (size_t)(b * DOUT + tid) * 4;
            ob[0] = bx.x; ob[1] = bx.y; ob[2] = bx.z; ob[3] = bx.w;
            out[BIMG * DOUT * 4 + b * DOUT + tid] = sc;
            out[BIMG * DOUT * 4 + BIMG * DOUT + b * DOUT + tid] = lb;
        }
    }

    // ================= final: reset barriers for next graph replay =====
    __syncthreads();
    if (tid == 0) {
        __threadfence();
        atomicAdd(&g_bar3, 1u);
        if (bid == 0) {
            volatile unsigned* vb = (volatile unsigned*)&g_bar3;
            while (*vb < NB) { }
            g_bar1 = 0; g_bar2 = 0; g_bar3 = 0;
            __threadfence();
        }
    }
}

// ---------------- launch ----------------
extern "C" void kernel_launch(void* const* d_in, const int* in_sizes, int n_in,
                              void* d_out, int out_size) {
    const float *logits = nullptr, *reg = nullptr, *props = nullptr;
    for (int i = 0; i < n_in; ++i) {
        if      (in_sizes[i] == BIMG * NPROP * NCLS)     logits = (const float*)d_in[i];
        else if (in_sizes[i] == BIMG * NPROP * NCLS * 4) reg    = (const float*)d_in[i];
        else if (in_sizes[i] == BIMG * NPROP * 4)        props  = (const float*)d_in[i];
    }
    k_fused<<<NB, NT>>>(logits, reg, props, (float*)d_out);
}